// round 9
// baseline (speedup 1.0000x reference)
#include <cuda_runtime.h>
#include <cuda_bf16.h>
#include <cstdint>

// ============================================================================
// IntegerCifar10Net R9: bf16 HMMA convs + ldmatrix + double-buffered,
// software-pipelined weight staging (3-tap groups). Exact integer arithmetic.
// ============================================================================

__device__ __forceinline__ int qlev(float w) {
    w = fminf(fmaxf(w, -1.0f), 1.0f);
    return (int)rintf(w * 7.0f);
}
__device__ __forceinline__ unsigned pack_bf16x2(float lo, float hi) {
    unsigned r;
    asm("cvt.rn.bf16x2.f32 %0, %1, %2;" : "=r"(r) : "f"(hi), "f"(lo));
    return r;
}
__device__ __forceinline__ unsigned smem_u32(const void* p) {
    return (unsigned)__cvta_generic_to_shared(p);
}
__device__ __forceinline__ void cp16(unsigned dst, const void* src, int szvalid) {
    asm volatile("cp.async.cg.shared.global [%0], [%1], 16, %2;"
                 :: "r"(dst), "l"(src), "r"(szvalid) : "memory");
}
__device__ __forceinline__ void cp_commit() {
    asm volatile("cp.async.commit_group;" ::: "memory");
}
__device__ __forceinline__ void cp_wait0() {
    asm volatile("cp.async.wait_group 0;" ::: "memory");
}
__device__ __forceinline__ void ldsm4(unsigned* r, unsigned addr) {
    asm volatile("ldmatrix.sync.aligned.m8n8.x4.shared.b16 {%0,%1,%2,%3}, [%4];"
                 : "=r"(r[0]), "=r"(r[1]), "=r"(r[2]), "=r"(r[3]) : "r"(addr));
}

// ---------------- scratch ----------------
__device__ __nv_bfloat16 g_bufA[512 * 32 * 32 * 64];
__device__ __nv_bfloat16 g_bufB[512 * 32 * 32 * 64];
__device__ float         g_qw1[64 * 3 * 9];
__device__ __nv_bfloat16 g_wb2[9 * 1 * 64 * 64];
__device__ __nv_bfloat16 g_wb3[9 * 1 * 128 * 64];
__device__ __nv_bfloat16 g_wb4[9 * 2 * 128 * 64];
__device__ __nv_bfloat16 g_wb5[9 * 2 * 256 * 64];
__device__ __nv_bfloat16 g_wb6[9 * 4 * 256 * 64];
__device__ int           g_wf1[512 * 1024];
__device__ signed char   g_wf2[10 * 512];
__device__ unsigned char g_fc1[512 * 512];

// ---------------- weight prep ----------------
__global__ void quant_w1_k(const float* __restrict__ w, float* __restrict__ qw, int n) {
    int i = blockIdx.x * blockDim.x + threadIdx.x;
    if (i < n) qw[i] = (float)qlev(w[i]) / 7.0f;
}
// OIHW float -> bf16 [kpos][ch][oc][64]
__global__ void pack_convw_bf16(const float* __restrict__ w, __nv_bfloat16* __restrict__ out,
                                int COUT, int CIN) {
    int idx = blockIdx.x * blockDim.x + threadIdx.x;
    int NCH = CIN / 64;
    if (idx >= COUT * 9 * CIN) return;
    int j = idx % 64;
    int t = idx / 64;
    int oc = t % COUT; t /= COUT;
    int ch = t % NCH;
    int kpos = t / NCH;
    out[idx] = __float2bfloat16((float)qlev(w[(oc * CIN + ch * 64 + j) * 9 + kpos]));
}
__global__ void pack_fc1_k(const float* __restrict__ w, int* __restrict__ out) {
    int idx = blockIdx.x * blockDim.x + threadIdx.x;
    if (idx >= 512 * 1024) return;
    int wi = idx % 1024, o = idx / 1024;
    int px = wi / 64, c4 = wi % 64;
    unsigned word = 0;
#pragma unroll
    for (int l = 0; l < 4; l++) {
        int k = (4 * c4 + l) * 16 + px;
        word |= (unsigned)(qlev(w[o * 4096 + k]) & 0xFF) << (8 * l);
    }
    out[idx] = (int)word;
}
__global__ void pack_fc2_k(const float* __restrict__ w, signed char* __restrict__ out) {
    int idx = blockIdx.x * blockDim.x + threadIdx.x;
    if (idx < 10 * 512) out[idx] = (signed char)qlev(w[idx]);
}

// ---------------- conv1: fp32 NCHW -> bf16 NHWC levels ----------------
__global__ void __launch_bounds__(1024)
conv1_kernel(const float* __restrict__ x, const float* __restrict__ qw,
             const float* __restrict__ g, const float* __restrict__ b,
             __nv_bfloat16* __restrict__ out) {
    __shared__ float s_in[3][34][34];
    __shared__ float s_w[16][27];
    const int tid = threadIdx.x;
    const int oy = tid / 32, ox = tid % 32;
    const int n = blockIdx.y;
    const int oc0 = blockIdx.x * 16;
    for (int i = tid; i < 3 * 34 * 34; i += 1024) {
        int t = i;
        int xx = t % 34; t /= 34;
        int yy = t % 34; t /= 34;
        int c = t;
        int yi = yy - 1, xi = xx - 1;
        float v = 0.0f;
        if ((unsigned)yi < 32u && (unsigned)xi < 32u)
            v = x[((n * 3 + c) * 32 + yi) * 32 + xi];
        s_in[c][yy][xx] = v;
    }
    for (int i = tid; i < 16 * 27; i += 1024)
        s_w[i / 27][i % 27] = qw[(oc0 + i / 27) * 27 + i % 27];
    __syncthreads();
    float acc[16];
#pragma unroll
    for (int o = 0; o < 16; o++) acc[o] = 0.0f;
#pragma unroll
    for (int c = 0; c < 3; c++) {
        float wv[9];
#pragma unroll
        for (int ky = 0; ky < 3; ky++)
#pragma unroll
            for (int kx = 0; kx < 3; kx++)
                wv[ky * 3 + kx] = s_in[c][oy + ky][ox + kx];
#pragma unroll
        for (int o = 0; o < 16; o++) {
            float a = acc[o];
#pragma unroll
            for (int k = 0; k < 9; k++) a = fmaf(wv[k], s_w[o][c * 9 + k], a);
            acc[o] = a;
        }
    }
    unsigned* ob = (unsigned*)(out + ((size_t)(n * 1024) + oy * 32 + ox) * 64 + oc0);
#pragma unroll
    for (int j = 0; j < 8; j++) {
        float lv[2];
#pragma unroll
        for (int l = 0; l < 2; l++) {
            int o = j * 2 + l;
            float p = acc[o] * g[oc0 + o] + b[oc0 + o];
            p = fminf(fmaxf(p, -1.0f), 1.0f);
            lv[l] = fmaxf(rintf(p * 7.0f), 0.0f);
        }
        ob[j] = pack_bf16x2(lv[0], lv[1]);
    }
}

// ---------------- bf16 HMMA conv (ldmatrix + pipelined weights) ----------------
__device__ __forceinline__ void mma_bf16(float* d, const unsigned* a, unsigned b0, unsigned b1) {
    asm volatile(
        "mma.sync.aligned.m16n8k16.row.col.f32.bf16.bf16.f32 "
        "{%0,%1,%2,%3},{%4,%5,%6,%7},{%8,%9},{%0,%1,%2,%3};"
        : "+f"(d[0]), "+f"(d[1]), "+f"(d[2]), "+f"(d[3])
        : "r"(a[0]), "r"(a[1]), "r"(a[2]), "r"(a[3]), "r"(b0), "r"(b1));
}

// act [n][H][W][CIN] bf16 ; weight [kpos][ch][oc][64] bf16
template <int H, int W, int TY, int TX, int NB, int CIN, int COUT>
__global__ void __launch_bounds__(256, 2)
conv_hmma(const __nv_bfloat16* __restrict__ in, const __nv_bfloat16* __restrict__ wq,
          const float* __restrict__ g, const float* __restrict__ bb,
          __nv_bfloat16* __restrict__ out) {
    constexpr int NCH = CIN / 64;
    constexpr int KCP = 144;                 // 128B chunk + 16B pad
    constexpr int PXT = TY * TX;
    constexpr int SIN_PIX = NB * (TY + 2) * (TX + 2);
    constexpr int WGRP = 3 * 64 * KCP;       // one 3-tap weight group

    extern __shared__ char smem[];
    char* s_in = smem;                       // SIN_PIX * KCP
    char* s_w0 = smem + SIN_PIX * KCP;       // group buffer 0
    char* s_w1 = s_w0 + WGRP;                // group buffer 1

    const int tid  = threadIdx.x;
    const int warp = tid >> 5, lane = tid & 31;
    const int oc0  = blockIdx.x * 64;
    const int ty0  = (blockIdx.y / (W / TX)) * TY;
    const int tx0  = (blockIdx.y % (W / TX)) * TX;
    const int n0   = blockIdx.z * NB;
    const char* inb = (const char*)in;
    const char* wqb = (const char*)wq;

    float acc[2][8][4];
#pragma unroll
    for (int mi = 0; mi < 2; mi++)
#pragma unroll
        for (int ni = 0; ni < 8; ni++)
#pragma unroll
            for (int j = 0; j < 4; j++) acc[mi][ni][j] = 0.0f;

    // ldmatrix per-lane base addresses
    unsigned Abase[2];
#pragma unroll
    for (int mi = 0; mi < 2; mi++) {
        int row_local = ((lane >> 3) & 1) * 8 + (lane & 7);
        int p = warp * 32 + mi * 16 + row_local;
        int nn = p / PXT, rem = p % PXT;
        int py = rem / TX, px = rem % TX;
        Abase[mi] = smem_u32(s_in) + ((nn * (TY + 2) + py) * (TX + 2) + px) * KCP
                    + (lane >> 4) * 16;
    }
    const unsigned blane = ((lane & 7) + (lane >> 4) * 8) * KCP + ((lane >> 3) & 1) * 16;

    // ---- staging helpers ----
    auto stageA = [&](int ch) {
        for (int u = tid; u < SIN_PIX * 8; u += 256) {
            int j   = u & 7;
            int pix = u >> 3;
            int xx  = pix % (TX + 2);
            int yy  = (pix / (TX + 2)) % (TY + 2);
            int nn  = pix / ((TX + 2) * (TY + 2));
            int gy = ty0 + yy - 1, gx = tx0 + xx - 1;
            bool ok = (unsigned)gy < (unsigned)H && (unsigned)gx < (unsigned)W;
            const char* src = ok
                ? inb + ((((size_t)(n0 + nn) * H + gy) * W + gx) * CIN + ch * 64 + j * 8) * 2
                : inb;
            cp16(smem_u32(s_in + pix * KCP + j * 16), src, ok ? 16 : 0);
        }
    };
    auto stageW = [&](int t0, int chw, char* dst) {   // 3 taps t0..t0+2
        for (int u = tid; u < 3 * 512; u += 256) {
            int kl  = u >> 9;
            int rem = u & 511;
            int r = rem >> 3, j = rem & 7;
            const char* src = wqb +
                (((size_t)((t0 + kl) * NCH + chw) * COUT + oc0 + r) * 64 + j * 8) * 2;
            cp16(smem_u32(dst + (kl * 64 + r) * KCP + j * 16), src, 16);
        }
    };

    unsigned wcur = smem_u32(s_w0), wnxt = smem_u32(s_w1);
    char *wcur_p = s_w0, *wnxt_p = s_w1;

    // prologue: A(0) + W group 0
    stageA(0);
    stageW(0, 0, wcur_p);
    cp_commit();
    cp_wait0();
    __syncthreads();

#pragma unroll 1
    for (int ch = 0; ch < NCH; ch++) {
#pragma unroll
        for (int gg = 0; gg < 3; gg++) {
            // prefetch next weight group (possibly next chunk's group 0)
            const bool lastIter = (ch == NCH - 1) && (gg == 2);
            if (!lastIter) {
                int nt0 = (gg == 2) ? 0 : (gg + 1) * 3;
                int nch = (gg == 2) ? ch + 1 : ch;
                stageW(nt0, nch, wnxt_p);
                cp_commit();
            }
            // compute 3 taps from wcur
#pragma unroll
            for (int kl = 0; kl < 3; kl++) {
                const int kpos = gg * 3 + kl;
                const int off0 = ((kpos / 3) * (TX + 2) + (kpos % 3)) * KCP;
#pragma unroll
                for (int ks = 0; ks < 4; ks++) {
                    const int off = off0 + ks * 32;
                    unsigned a0[4], a1[4];
                    ldsm4(a0, Abase[0] + off);
                    ldsm4(a1, Abase[1] + off);
#pragma unroll
                    for (int np = 0; np < 4; np++) {
                        unsigned b[4];
                        ldsm4(b, wcur + blane + (kl * 64 + np * 16) * KCP + ks * 32);
                        mma_bf16(acc[0][2 * np],     a0, b[0], b[1]);
                        mma_bf16(acc[0][2 * np + 1], a0, b[2], b[3]);
                        mma_bf16(acc[1][2 * np],     a1, b[0], b[1]);
                        mma_bf16(acc[1][2 * np + 1], a1, b[2], b[3]);
                    }
                }
            }
            cp_wait0();
            __syncthreads();
            // stage next chunk's A (exposed; single A buffer)
            if (gg == 2 && ch + 1 < NCH) {
                stageA(ch + 1);
                cp_commit();
                cp_wait0();
                __syncthreads();
            }
            // swap weight buffers
            unsigned tu = wcur; wcur = wnxt; wnxt = tu;
            char* tp = wcur_p; wcur_p = wnxt_p; wnxt_p = tp;
        }
    }

    // ---- epilogue: quantized activation -> bf16 NHWC ----
#pragma unroll
    for (int mi = 0; mi < 2; mi++) {
#pragma unroll
        for (int half = 0; half < 2; half++) {
            int row = warp * 32 + mi * 16 + (lane >> 2) + half * 8;
            int nn = row / PXT, rem = row % PXT;
            int py = rem / TX, px = rem % TX;
            size_t ob = (((size_t)(n0 + nn) * H + ty0 + py) * W + tx0 + px) * COUT + oc0;
#pragma unroll
            for (int ni = 0; ni < 8; ni++) {
                int col = ni * 8 + (lane & 3) * 2;
                float lv[2];
#pragma unroll
                for (int l = 0; l < 2; l++) {
                    float y = acc[mi][ni][half * 2 + l] / 49.0f;
                    float p = y * g[oc0 + col + l] + bb[oc0 + col + l];
                    p = fminf(fmaxf(p, -1.0f), 1.0f);
                    lv[l] = fmaxf(rintf(p * 7.0f), 0.0f);
                }
                *(unsigned*)((char*)out + (ob + col) * 2) = pack_bf16x2(lv[0], lv[1]);
            }
        }
    }
}

// ---------------- pools ----------------
__global__ void pool_bf16(const unsigned* __restrict__ in, unsigned* __restrict__ out,
                          int Wo, int C2, int total) {
    int idx = blockIdx.x * blockDim.x + threadIdx.x;
    if (idx >= total) return;
    int c2 = idx % C2;
    int t = idx / C2;
    int xo = t % Wo; t /= Wo;
    int yo = t % Wo;
    int n = t / Wo;
    int Wi = 2 * Wo;
    const unsigned* p = in + (((size_t)n * Wi + 2 * yo) * Wi + 2 * xo) * C2 + c2;
    __nv_bfloat162 a = *(const __nv_bfloat162*)&p[0];
    __nv_bfloat162 b = *(const __nv_bfloat162*)&p[C2];
    __nv_bfloat162 c = *(const __nv_bfloat162*)&p[(size_t)Wi * C2];
    __nv_bfloat162 d = *(const __nv_bfloat162*)&p[(size_t)Wi * C2 + C2];
    __nv_bfloat162 m = __hmax2(__hmax2(a, b), __hmax2(c, d));
    out[idx] = *(unsigned*)&m;
}
__global__ void pool3_int8(const unsigned* __restrict__ in, unsigned* __restrict__ out,
                           int total) {
    int idx = blockIdx.x * blockDim.x + threadIdx.x;
    if (idx >= total) return;
    int c4 = idx % 64;
    int px = (idx / 64) % 16;
    int n = idx / 1024;
    int xo = px % 4, yo = px / 4;
    unsigned word = 0;
#pragma unroll
    for (int h = 0; h < 2; h++) {
        int c2 = c4 * 2 + h;
        const unsigned* p = in + (((size_t)n * 8 + 2 * yo) * 8 + 2 * xo) * 128 + c2;
        __nv_bfloat162 a = *(const __nv_bfloat162*)&p[0];
        __nv_bfloat162 b = *(const __nv_bfloat162*)&p[128];
        __nv_bfloat162 c = *(const __nv_bfloat162*)&p[8 * 128];
        __nv_bfloat162 d = *(const __nv_bfloat162*)&p[8 * 128 + 128];
        __nv_bfloat162 m = __hmax2(__hmax2(a, b), __hmax2(c, d));
        int v0 = (int)__low2float(m);
        int v1 = (int)__high2float(m);
        word |= ((unsigned)v0 << (16 * h)) | ((unsigned)v1 << (16 * h + 8));
    }
    out[idx] = word;
}

// ---------------- FC ----------------
__global__ void fc1_kernel(const int* __restrict__ h, const int* __restrict__ w,
                           const float* __restrict__ g, const float* __restrict__ b,
                           unsigned char* __restrict__ out) {
    __shared__ int sa[16][17];
    __shared__ int sw[16][17];
    const int tx = threadIdx.x, ty = threadIdx.y;
    const int n = blockIdx.y * 16 + ty;
    const int o = blockIdx.x * 16 + tx;
    int acc = 0;
    for (int m0 = 0; m0 < 1024; m0 += 16) {
        sa[ty][tx] = h[(blockIdx.y * 16 + ty) * 1024 + m0 + tx];
        sw[ty][tx] = w[(blockIdx.x * 16 + ty) * 1024 + m0 + tx];
        __syncthreads();
#pragma unroll
        for (int mm = 0; mm < 16; mm++) acc = __dp4a(sa[ty][mm], sw[tx][mm], acc);
        __syncthreads();
    }
    float y = (float)acc / 49.0f;
    float p = y * g[o] + b[o];
    p = fminf(fmaxf(p, -1.0f), 1.0f);
    int lev = max((int)rintf(p * 7.0f), 0);
    out[n * 512 + o] = (unsigned char)lev;
}
__global__ void fc2_kernel(const unsigned char* __restrict__ h,
                           const signed char* __restrict__ w,
                           const float* __restrict__ g, const float* __restrict__ b,
                           float* __restrict__ out) {
    const int n = blockIdx.x;
    const int lane = threadIdx.x;
    for (int o = 0; o < 10; o++) {
        int acc = 0;
        for (int k = lane; k < 512; k += 32)
            acc += (int)h[n * 512 + k] * (int)w[o * 512 + k];
#pragma unroll
        for (int off = 16; off > 0; off >>= 1)
            acc += __shfl_xor_sync(0xFFFFFFFFu, acc, off);
        if (lane == 0) {
            float y = (float)acc / 49.0f;
            float p = y * g[o] + b[o];
            p = fminf(fmaxf(p, -1.0f), 1.0f);
            out[n * 10 + o] = (float)((int)rintf(p * 7.0f)) / 7.0f;
        }
    }
}

// ---------------- launch ----------------
extern "C" void kernel_launch(void* const* d_in, const int* in_sizes, int n_in,
                              void* d_out, int out_size) {
    const float* x = (const float*)d_in[0];
    const float *w1 = (const float*)d_in[1], *g1 = (const float*)d_in[2], *b1 = (const float*)d_in[3];
    const float *w2 = (const float*)d_in[4], *g2 = (const float*)d_in[5], *b2 = (const float*)d_in[6];
    const float *w3 = (const float*)d_in[7], *g3 = (const float*)d_in[8], *b3 = (const float*)d_in[9];
    const float *w4 = (const float*)d_in[10], *g4 = (const float*)d_in[11], *b4 = (const float*)d_in[12];
    const float *w5 = (const float*)d_in[13], *g5 = (const float*)d_in[14], *b5 = (const float*)d_in[15];
    const float *w6 = (const float*)d_in[16], *g6 = (const float*)d_in[17], *b6 = (const float*)d_in[18];
    const float *wf1 = (const float*)d_in[19], *gf1 = (const float*)d_in[20], *bf1 = (const float*)d_in[21];
    const float *wf2 = (const float*)d_in[22], *gf2 = (const float*)d_in[23], *bf2 = (const float*)d_in[24];

    void *bufA, *bufB, *qw1, *w2p, *w3p, *w4p, *w5p, *w6p, *wf1p, *wf2p, *fc1o;
    cudaGetSymbolAddress(&bufA, g_bufA);
    cudaGetSymbolAddress(&bufB, g_bufB);
    cudaGetSymbolAddress(&qw1, g_qw1);
    cudaGetSymbolAddress(&w2p, g_wb2);
    cudaGetSymbolAddress(&w3p, g_wb3);
    cudaGetSymbolAddress(&w4p, g_wb4);
    cudaGetSymbolAddress(&w5p, g_wb5);
    cudaGetSymbolAddress(&w6p, g_wb6);
    cudaGetSymbolAddress(&wf1p, g_wf1);
    cudaGetSymbolAddress(&wf2p, g_wf2);
    cudaGetSymbolAddress(&fc1o, g_fc1);

    auto k2 = conv_hmma<32, 32, 16, 16, 1, 64, 64>;
    auto k3 = conv_hmma<16, 16, 16, 16, 1, 64, 128>;
    auto k4 = conv_hmma<16, 16, 16, 16, 1, 128, 128>;
    auto k5 = conv_hmma<8, 8, 8, 8, 4, 128, 256>;
    auto k6 = conv_hmma<8, 8, 8, 8, 4, 256, 256>;
    const int smA = (1 * 18 * 18) * 144 + 2 * 3 * 64 * 144;   // 46656 + 55296 = 101952
    const int smB = (4 * 10 * 10) * 144 + 2 * 3 * 64 * 144;   // 57600 + 55296 = 112896
    cudaFuncSetAttribute(k2, cudaFuncAttributeMaxDynamicSharedMemorySize, smA);
    cudaFuncSetAttribute(k3, cudaFuncAttributeMaxDynamicSharedMemorySize, smA);
    cudaFuncSetAttribute(k4, cudaFuncAttributeMaxDynamicSharedMemorySize, smA);
    cudaFuncSetAttribute(k5, cudaFuncAttributeMaxDynamicSharedMemorySize, smB);
    cudaFuncSetAttribute(k6, cudaFuncAttributeMaxDynamicSharedMemorySize, smB);

    quant_w1_k<<<7, 256>>>(w1, (float*)qw1, 1728);
    pack_convw_bf16<<<(64 * 9 * 64 + 255) / 256, 256>>>(w2, (__nv_bfloat16*)w2p, 64, 64);
    conv1_kernel<<<dim3(4, 512), 1024>>>(x, (const float*)qw1, g1, b1, (__nv_bfloat16*)bufA);
    // L2: 64->64 @32, A->B
    k2<<<dim3(1, 4, 512), 256, smA>>>((const __nv_bfloat16*)bufA, (const __nv_bfloat16*)w2p,
                                      g2, b2, (__nv_bfloat16*)bufB);
    pack_convw_bf16<<<(128 * 9 * 64 + 255) / 256, 256>>>(w3, (__nv_bfloat16*)w3p, 128, 64);
    pack_convw_bf16<<<(128 * 9 * 128 + 255) / 256, 256>>>(w4, (__nv_bfloat16*)w4p, 128, 128);
    pack_convw_bf16<<<(256 * 9 * 128 + 255) / 256, 256>>>(w5, (__nv_bfloat16*)w5p, 256, 128);
    pack_convw_bf16<<<(256 * 9 * 256 + 255) / 256, 256>>>(w6, (__nv_bfloat16*)w6p, 256, 256);
    pack_fc1_k<<<(512 * 1024 + 255) / 256, 256>>>(wf1, (int*)wf1p);
    pack_fc2_k<<<20, 256>>>(wf2, (signed char*)wf2p);
    {   // pool 32->16 (C2=32): B->A
        int total = 512 * 16 * 16 * 32;
        pool_bf16<<<(total + 255) / 256, 256>>>((const unsigned*)bufB, (unsigned*)bufA, 16, 32, total);
    }
    // L3: 64->128 @16, A->B
    k3<<<dim3(2, 1, 512), 256, smA>>>((const __nv_bfloat16*)bufA, (const __nv_bfloat16*)w3p,
                                      g3, b3, (__nv_bfloat16*)bufB);
    // L4: 128->128 @16, B->A
    k4<<<dim3(2, 1, 512), 256, smA>>>((const __nv_bfloat16*)bufB, (const __nv_bfloat16*)w4p,
                                      g4, b4, (__nv_bfloat16*)bufA);
    {   // pool 16->8 (C2=64): A->B
        int total = 512 * 8 * 8 * 64;
        pool_bf16<<<(total + 255) / 256, 256>>>((const unsigned*)bufA, (unsigned*)bufB, 8, 64, total);
    }
    // L5: 128->256 @8, B->A
    k5<<<dim3(4, 1, 128), 256, smB>>>((const __nv_bfloat16*)bufB, (const __nv_bfloat16*)w5p,
                                      g5, b5, (__nv_bfloat16*)bufA);
    // L6: 256->256 @8, A->B
    k6<<<dim3(4, 1, 128), 256, smB>>>((const __nv_bfloat16*)bufA, (const __nv_bfloat16*)w6p,
                                      g6, b6, (__nv_bfloat16*)bufB);
    {   // pool 8->4 -> packed int8 words: B->A
        int total = 512 * 16 * 64;
        pool3_int8<<<(total + 255) / 256, 256>>>((const unsigned*)bufB, (unsigned*)bufA, total);
    }

    fc1_kernel<<<dim3(32, 32), dim3(16, 16)>>>((const int*)bufA, (const int*)wf1p, gf1, bf1,
                                               (unsigned char*)fc1o);
    fc2_kernel<<<512, 32>>>((const unsigned char*)fc1o, (const signed char*)wf2p, gf2, bf2,
                            (float*)d_out);
}